// round 5
// baseline (speedup 1.0000x reference)
#include <cuda_runtime.h>

// Problem constants (fixed shapes from reference)
#define BATCH 32
#define IN_H  128
#define IN_W  512
#define CHAN  32
#define OUT_H 64
#define OUT_W 256

// Grid: (OUT_W/32, OUT_H, BATCH), block 256 threads.
// Block covers 32 consecutive output-x points; 8 threads per point,
// each owning one float4 channel group. All index math is 32-bit,
// no division/modulo anywhere.

__global__ void __launch_bounds__(256)
stn_bilinear_kernel(const float* __restrict__ image,
                    const float* __restrict__ theta,
                    float* __restrict__ out)
{
    const int cg = threadIdx.x & 7;            // channel group 0..7
    const int wx = (blockIdx.x << 5) + (threadIdx.x >> 3);
    const int hy = blockIdx.y;
    const int b  = blockIdx.z;

    // sampling grid in [-1, 1] (linspace, endpoint inclusive) — same math as R1
    float xg = -1.0f + 2.0f * (float)wx / (float)(OUT_W - 1);
    float yg = -1.0f + 2.0f * (float)hy / (float)(OUT_H - 1);

    // theta[b] as 2x3; reference's debug hack: zero row 1 of batch 0, row 0 of batch 1
    const float* th = theta + b * 6;
    float t00 = __ldg(th + 0), t01 = __ldg(th + 1), t02 = __ldg(th + 2);
    float t10 = __ldg(th + 3), t11 = __ldg(th + 4), t12 = __ldg(th + 5);
    if (b == 0) { t10 = 0.0f; t11 = 0.0f; t12 = 0.0f; }
    if (b == 1) { t00 = 0.0f; t01 = 0.0f; t02 = 0.0f; }

    float cx = t00 * xg + t01 * yg + t02;
    float cy = t10 * xg + t11 * yg + t12;

    float x = 0.5f * (cx + 1.0f) * (float)IN_W;   // uses W, not W-1 (matches source)
    float y = 0.5f * (cy + 1.0f) * (float)IN_H;

    // truncation toward zero (matches jnp astype(int32))
    int x0 = (int)x;
    int y0 = (int)y;
    int x1 = x0 + 1;
    int y1 = y0 + 1;
    // clip BEFORE computing float weights (matches reference ordering)
    x0 = min(max(x0, 0), IN_W - 1);
    x1 = min(max(x1, 0), IN_W - 1);
    y0 = min(max(y0, 0), IN_H - 1);
    y1 = min(max(y1, 0), IN_H - 1);

    float x0f = (float)x0, x1f = (float)x1;
    float y0f = (float)y0, y1f = (float)y1;

    float wA = (x1f - x) * (y1f - y);
    float wB = (x1f - x) * (y - y0f);
    float wC = (x - x0f) * (y1f - y);
    float wD = (x - x0f) * (y - y0f);

    // 32-bit addressing: image has 2,097,152 pixels * 8 float4 = 16.7M < 2^31
    const float4* __restrict__ img4 = (const float4*)image;
    const unsigned basePix = (unsigned)b * (IN_H * IN_W);
    const unsigned row0 = basePix + (unsigned)y0 * IN_W;   // row of y0
    const unsigned row1 = basePix + (unsigned)y1 * IN_W;   // row of y1

    const unsigned iA = ((row0 + (unsigned)x0) << 3) + cg;
    const unsigned iB = ((row1 + (unsigned)x0) << 3) + cg;
    const unsigned iC = ((row0 + (unsigned)x1) << 3) + cg;
    const unsigned iD = ((row1 + (unsigned)x1) << 3) + cg;

    float4 pA = __ldg(img4 + iA);
    float4 pB = __ldg(img4 + iB);
    float4 pC = __ldg(img4 + iC);
    float4 pD = __ldg(img4 + iD);

    float4 res;
    res.x = pA.x * wA + pB.x * wB + pC.x * wC + pD.x * wD;
    res.y = pA.y * wA + pB.y * wB + pC.y * wC + pD.y * wD;
    res.z = pA.z * wA + pB.z * wB + pC.z * wC + pD.z * wD;
    res.w = pA.w * wA + pB.w * wB + pC.w * wC + pD.w * wD;

    float4* __restrict__ out4 = (float4*)out;
    const unsigned oIdx = ((((unsigned)b * OUT_H + hy) * OUT_W + wx) << 3) + cg;
    out4[oIdx] = res;
}

extern "C" void kernel_launch(void* const* d_in, const int* in_sizes, int n_in,
                              void* d_out, int out_size)
{
    const float* image = (const float*)d_in[0];
    const float* theta = (const float*)d_in[1];
    float*       out   = (float*)d_out;

    dim3 grid(OUT_W / 32, OUT_H, BATCH);
    dim3 block(256);
    stn_bilinear_kernel<<<grid, block>>>(image, theta, out);
}

// round 6
// speedup vs baseline: 1.2998x; 1.2998x over previous
#include <cuda_runtime.h>

// Problem constants (fixed shapes from reference)
#define BATCH 32
#define IN_H  128
#define IN_W  512
#define CHAN  32
#define OUT_H 64
#define OUT_W 256

// 1D grid (R1's proven layout). Each thread handles ONE channel-group (float4)
// for TWO output points: (b, hy, wx) and (b, hy+32, wx). Theta regs, xg, and
// all index decomposition are shared between the two points.
// Threads = 32*64*256*8 / 2 = 2,097,152 -> 8192 blocks of 256.

__global__ void __launch_bounds__(256)
stn_bilinear_kernel(const float* __restrict__ image,
                    const float* __restrict__ theta,
                    float* __restrict__ out)
{
    const unsigned t  = blockIdx.x * 256u + threadIdx.x;
    const unsigned cg = t & 7u;          // channel group 0..7
    const unsigned n  = t >> 3;          // point index (lower half of hy)
    const unsigned wx = n & 255u;        // OUT_W = 256
    const unsigned r  = n >> 8;
    const unsigned hy = r & 31u;         // 0..31 (second point = hy+32)
    const unsigned b  = r >> 5;          // 0..31

    // sampling grid in [-1,1]; multiply by reciprocal instead of divide
    const float xg  = (float)wx * (2.0f / 255.0f) - 1.0f;
    const float yg0 = (float)hy * (2.0f / 63.0f) - 1.0f;
    const float yg1 = (float)(hy + 32u) * (2.0f / 63.0f) - 1.0f;

    // theta[b] as 2x3; reference hack: zero row 1 of batch 0, row 0 of batch 1
    const float* th = theta + b * 6u;
    float t00 = __ldg(th + 0), t01 = __ldg(th + 1), t02 = __ldg(th + 2);
    float t10 = __ldg(th + 3), t11 = __ldg(th + 4), t12 = __ldg(th + 5);
    if (b == 0u) { t10 = 0.0f; t11 = 0.0f; t12 = 0.0f; }
    if (b == 1u) { t00 = 0.0f; t01 = 0.0f; t02 = 0.0f; }

    const float4* __restrict__ img4 = (const float4*)image;
    float4* __restrict__ out4 = (float4*)out;
    const unsigned basePix = b * (unsigned)(IN_H * IN_W);
    const unsigned oBase   = ((b * (unsigned)OUT_H + hy) * (unsigned)OUT_W + wx) * 8u + cg;

    #pragma unroll
    for (int half = 0; half < 2; ++half) {
        const float yg = half ? yg1 : yg0;

        float cx = t00 * xg + t01 * yg + t02;
        float cy = t10 * xg + t11 * yg + t12;

        float x = 0.5f * (cx + 1.0f) * (float)IN_W;   // uses W, not W-1
        float y = 0.5f * (cy + 1.0f) * (float)IN_H;

        // truncation toward zero (matches astype(int32))
        int x0 = (int)x;
        int y0 = (int)y;
        int x1 = x0 + 1;
        int y1 = y0 + 1;
        // clip BEFORE computing float weights (matches reference ordering)
        x0 = min(max(x0, 0), IN_W - 1);
        x1 = min(max(x1, 0), IN_W - 1);
        y0 = min(max(y0, 0), IN_H - 1);
        y1 = min(max(y1, 0), IN_H - 1);

        float x0f = (float)x0, x1f = (float)x1;
        float y0f = (float)y0, y1f = (float)y1;

        float wA = (x1f - x) * (y1f - y);
        float wB = (x1f - x) * (y - y0f);
        float wC = (x - x0f) * (y1f - y);
        float wD = (x - x0f) * (y - y0f);

        const unsigned row0 = basePix + (unsigned)y0 * (unsigned)IN_W;
        const unsigned row1 = basePix + (unsigned)y1 * (unsigned)IN_W;

        float4 pA = __ldg(img4 + (((row0 + (unsigned)x0) << 3) + cg));
        float4 pB = __ldg(img4 + (((row1 + (unsigned)x0) << 3) + cg));
        float4 pC = __ldg(img4 + (((row0 + (unsigned)x1) << 3) + cg));
        float4 pD = __ldg(img4 + (((row1 + (unsigned)x1) << 3) + cg));

        float4 res;
        res.x = pA.x * wA + pB.x * wB + pC.x * wC + pD.x * wD;
        res.y = pA.y * wA + pB.y * wB + pC.y * wC + pD.y * wD;
        res.z = pA.z * wA + pB.z * wB + pC.z * wC + pD.z * wD;
        res.w = pA.w * wA + pB.w * wB + pC.w * wC + pD.w * wD;

        out4[oBase + (unsigned)half * (32u * OUT_W * 8u)] = res;
    }
}

extern "C" void kernel_launch(void* const* d_in, const int* in_sizes, int n_in,
                              void* d_out, int out_size)
{
    const float* image = (const float*)d_in[0];
    const float* theta = (const float*)d_in[1];
    float*       out   = (float*)d_out;

    const unsigned total_threads = (unsigned)BATCH * OUT_H * OUT_W * (CHAN / 4) / 2u;
    stn_bilinear_kernel<<<total_threads / 256u, 256>>>(image, theta, out);
}